// round 14
// baseline (speedup 1.0000x reference)
#include <cuda_runtime.h>
#include <cuda_fp16.h>
#include <math.h>
#include <stdint.h>

#define Bmax 4
#define C_ 64
#define H_ 128
#define W_ 128
#define O_ 64
#define K_ 9
#define HW_ (H_*W_)

__device__ __forceinline__ uint32_t cvt_h2(float hi, float lo) {
    uint32_t r; asm("cvt.rn.f16x2.f32 %0, %1, %2;" : "=r"(r) : "f"(hi), "f"(lo)); return r;
}
__device__ __forceinline__ void mma16(float4 &d, uint32_t a0, uint32_t a1, uint32_t a2, uint32_t a3,
                                      uint32_t b0, uint32_t b1) {
    asm("mma.sync.aligned.m16n8k16.row.col.f32.f16.f16.f32 "
        "{%0,%1,%2,%3},{%4,%5,%6,%7},{%8,%9},{%0,%1,%2,%3};"
        : "+f"(d.x), "+f"(d.y), "+f"(d.z), "+f"(d.w)
        : "r"(a0), "r"(a1), "r"(a2), "r"(a3), "r"(b0), "r"(b1));
}
__device__ __forceinline__ void ldsm4(uint32_t &a0, uint32_t &a1, uint32_t &a2, uint32_t &a3,
                                      uint32_t addr) {
    asm volatile("ldmatrix.sync.aligned.m8n8.x4.shared.b16 {%0,%1,%2,%3}, [%4];"
                 : "=r"(a0), "=r"(a1), "=r"(a2), "=r"(a3) : "r"(addr));
}

// ---------------- device scratch ----------------
__device__ __align__(16) __half g_xh[Bmax*HW_*C_ + 16384];  // NHWC x (fp16), padded
__device__ uint4 g_wt3h4[K_*4*4*32];          // main: [k][ks(4)][j2(4)][lane]
__device__ uint4 g_w1h4[K_*4*2*32];           // om:   [kk(9)][ks(4)][j2(2)][lane]

// ---------------- merged prep: transpose->fp16 NHWC + repack ----------------
#define NT_BLKS 1024
#define NREP4 (K_*4*4*32 + K_*4*2*32)
#define NREP_BLKS ((NREP4 + 255)/256)

__global__ __launch_bounds__(256)
void k_prep(const float* __restrict__ x, const float* __restrict__ wgt,
            const float* __restrict__ omw) {
    int bid = blockIdx.x;
    if (bid < NT_BLKS) {
        __shared__ float t[2][2][32][33];
        int wb = bid & 3;
        int h0 = ((bid >> 2) & 63) * 2;
        int b  = bid >> 8;
        int w0 = wb * 32;
        int tid = threadIdx.x;
        int r  = tid >> 3;
        int q  = tid & 7;
#pragma unroll
        for (int hh = 0; hh < 2; hh++) {
            float4 v0 = *(const float4*)(x + ((size_t)(b*C_ + r     )*H_ + h0 + hh)*W_ + w0 + q*4);
            float4 v1 = *(const float4*)(x + ((size_t)(b*C_ + 32 + r)*H_ + h0 + hh)*W_ + w0 + q*4);
            t[hh][0][r][q*4] = v0.x; t[hh][0][r][q*4+1] = v0.y; t[hh][0][r][q*4+2] = v0.z; t[hh][0][r][q*4+3] = v0.w;
            t[hh][1][r][q*4] = v1.x; t[hh][1][r][q*4+1] = v1.y; t[hh][1][r][q*4+2] = v1.z; t[hh][1][r][q*4+3] = v1.w;
        }
        __syncthreads();
#pragma unroll
        for (int hh = 0; hh < 2; hh++) {
            float4 o0, o1;
            o0.x = t[hh][0][q*4][r]; o0.y = t[hh][0][q*4+1][r]; o0.z = t[hh][0][q*4+2][r]; o0.w = t[hh][0][q*4+3][r];
            o1.x = t[hh][1][q*4][r]; o1.y = t[hh][1][q*4+1][r]; o1.z = t[hh][1][q*4+2][r]; o1.w = t[hh][1][q*4+3][r];
            __half* dst = g_xh + ((size_t)(b*H_ + h0 + hh)*W_ + w0 + r)*C_;
            *(uint2*)(dst + q*4)      = make_uint2(cvt_h2(o0.y, o0.x), cvt_h2(o0.w, o0.z));
            *(uint2*)(dst + 32 + q*4) = make_uint2(cvt_h2(o1.y, o1.x), cvt_h2(o1.w, o1.z));
        }
    } else {
        int f = (bid - NT_BLKS)*256 + threadIdx.x;
        if (f < K_*4*4*32) {              // main weights: [k][ks][j2(2b)][lane(5b)]
            int lane = f & 31;
            int j2 = (f >> 5) & 3;
            int ks = (f >> 7) & 3;
            int k  = f >> 9;
            int c0 = ks*16 + 2*(lane & 3);
            uint4 r;
            {
                int o = (2*j2)*8 + (lane >> 2);
                const float* wb2 = wgt + (size_t)o*C_*K_;
                r.x = cvt_h2(wb2[(c0+1)*K_ + k], wb2[c0*K_ + k]);
                r.y = cvt_h2(wb2[(c0+9)*K_ + k], wb2[(c0+8)*K_ + k]);
            }
            {
                int o = (2*j2+1)*8 + (lane >> 2);
                const float* wb2 = wgt + (size_t)o*C_*K_;
                r.z = cvt_h2(wb2[(c0+1)*K_ + k], wb2[c0*K_ + k]);
                r.w = cvt_h2(wb2[(c0+9)*K_ + k], wb2[(c0+8)*K_ + k]);
            }
            g_wt3h4[f] = r;
        } else if (f < NREP4) {           // om weights: [kk][ks(2b)][j2(1b)][lane(5b)]
            int f2 = f - K_*4*4*32;
            int lane = f2 & 31;
            int j2 = (f2 >> 5) & 1;
            int ks = (f2 >> 6) & 3;
            int kk = f2 >> 8;
            int c0 = ks*16 + 2*(lane & 3);
            uint4 r = make_uint4(0, 0, 0, 0);
            {
                int oc = (2*j2)*8 + (lane >> 2);
                if (oc < 27) {
                    const float* wb2 = omw + (size_t)oc*C_*K_;
                    r.x = cvt_h2(wb2[(c0+1)*K_ + kk], wb2[c0*K_ + kk]);
                    r.y = cvt_h2(wb2[(c0+9)*K_ + kk], wb2[(c0+8)*K_ + kk]);
                }
            }
            {
                int oc = (2*j2+1)*8 + (lane >> 2);
                if (oc < 27) {
                    const float* wb2 = omw + (size_t)oc*C_*K_;
                    r.z = cvt_h2(wb2[(c0+1)*K_ + kk], wb2[c0*K_ + kk]);
                    r.w = cvt_h2(wb2[(c0+9)*K_ + kk], wb2[(c0+8)*K_ + kk]);
                }
            }
            g_w1h4[f2] = r;
        }
    }
}

// ---------------- fused DCN: one block per (b, h, half-row of 64 px), 128 threads ----------------
// smem byte layout (35.6 KB -> 5 CTAs/SM)
#define SM_XS  0        // 9504  B : A tile half[66 px][72 c] (pitch 144B); om_s float[64][36] unions
#define SM_B   9504     // 12288 B : B fragments (ph1: 3 kx x 4KB; ph3: 8KB)
#define SM_SW  21792    // 9216  B : float4[9][64] corner weights
#define SM_I0  31008    // 2304  B : int[9][64]
#define SM_DD  33312    // 2304  B : int[9][64]
#define SM_TOT 35616

__global__ __launch_bounds__(128, 5)
void k_dcn(const float* __restrict__ bias, const float* __restrict__ om_bias,
           float* __restrict__ out) {
    extern __shared__ char sm[];
    uint4*    xs4   = (uint4*)(sm + SM_XS);      // row pitch 9 uint4
    float*    om_s  = (float*)(sm + SM_XS);      // stride 36 floats (144B pitch)
    uint4*    bB4   = (uint4*)(sm + SM_B);
    float4*   s_w   = (float4*)(sm + SM_SW);
    int*      s_i0  = (int*)(sm + SM_I0);
    int*      s_d   = (int*)(sm + SM_DD);

    const int tid  = threadIdx.x;
    const int lane = tid & 31;
    const int w    = tid >> 5;                   // 0..3
    const int tg   = lane >> 2;
    const int tig  = lane & 3;
    const int hf   = blockIdx.x & 1;
    const int h    = blockIdx.x >> 1;
    const int b    = blockIdx.y;
    const int w0px = hf*64;
    const int row0 = w*16 + tg;                  // local px band 0..63
    const __half* xh = g_xh + (size_t)b*HW_*C_;

    const uint32_t smb = (uint32_t)__cvta_generic_to_shared(sm);
    const int laneRow  = ((lane >> 3) & 1)*8 + (lane & 7);
    const int chunkOff = (lane >> 4)*16;
    const uint32_t aBase = smb + SM_XS + (uint32_t)(w*16 + laneRow)*144 + chunkOff;

    // ---------- Phase 1: offset/mask conv (64px x 32oc x 576), 3 row-stagings ----------
    float4 acc1[4];
#pragma unroll
    for (int j = 0; j < 4; j++) acc1[j] = make_float4(0.f, 0.f, 0.f, 0.f);

    for (int ky = 0; ky < 3; ky++) {
        int yy = h + ky - 1;
        // stage 66 window rows: r = 0..65, xx = w0px + r - 1
        for (int e = tid; e < 528; e += 128) {
            int c8 = e & 7, r = e >> 3;
            int xx = w0px + r - 1;
            uint4 v = make_uint4(0, 0, 0, 0);
            if (yy >= 0 && yy < H_ && xx >= 0 && xx < W_)
                v = *(const uint4*)(xh + ((size_t)yy*W_ + xx)*C_ + c8*8);
            xs4[r*9 + c8] = v;
        }
        {
            const uint4* src = g_w1h4 + (size_t)ky*3*256;
            for (int e = tid; e < 768; e += 128) bB4[e] = src[e];
        }
        __syncthreads();
#pragma unroll
        for (int ks = 0; ks < 4; ks++) {
#pragma unroll
            for (int kx = 0; kx < 3; kx++) {
                uint32_t a0, a1, a2, a3;
                ldsm4(a0, a1, a2, a3, aBase + kx*144 + ks*32);
#pragma unroll
                for (int j2 = 0; j2 < 2; j2++) {
                    uint4 bf = bB4[kx*256 + (ks*2 + j2)*32 + lane];
                    mma16(acc1[2*j2],     a0, a1, a2, a3, bf.x, bf.y);
                    mma16(acc1[2*j2 + 1], a0, a1, a2, a3, bf.z, bf.w);
                }
            }
        }
        __syncthreads();
    }

    // ---------- Phase 2a: write om fragments to smem (stride 36 floats) ----------
#pragma unroll
    for (int j = 0; j < 4; j++) {
        int col = j*8 + tig*2;
        *(float2*)(om_s + row0*36 + col)     = make_float2(acc1[j].x, acc1[j].y);
        *(float2*)(om_s + (row0+8)*36 + col) = make_float2(acc1[j].z, acc1[j].w);
    }
    __syncthreads();

    // ---------- Phase 2b: bilinear sampling prep per (px, k) ----------
    for (int e = tid; e < 576; e += 128) {
        int px = e & 63, k = e >> 6;
        int gx = w0px + px;
        int ky = k / 3, kx = k - 3*ky;
        float oy = om_s[px*36 + k]      + __ldg(om_bias + k);
        float ox = om_s[px*36 + 9 + k]  + __ldg(om_bias + 9 + k);
        float mz = om_s[px*36 + 18 + k] + __ldg(om_bias + 18 + k);
        float mk = 1.f / (1.f + expf(-mz));
        float pyf = oy + (float)(h - 1 + ky);
        float pxf = ox + (float)(gx - 1 + kx);
        float y0f = floorf(pyf), x0f = floorf(pxf);
        float ly = pyf - y0f, lx = pxf - x0f;
        int y0 = (int)y0f, x0 = (int)x0f;
        bool vy0 = (y0 >= 0)   & (y0 < H_);
        bool vy1 = (y0 >= -1)  & (y0 < H_-1);
        bool vx0 = (x0 >= 0)   & (x0 < W_);
        bool vx1 = (x0 >= -1)  & (x0 < W_-1);
        float w00 = (1.f-ly)*(1.f-lx)*mk * (float)(vy0 & vx0);
        float w01 = (1.f-ly)*lx*mk       * (float)(vy0 & vx1);
        float w10 = ly*(1.f-lx)*mk       * (float)(vy1 & vx0);
        float w11 = ly*lx*mk             * (float)(vy1 & vx1);
        int cy0 = min(max(y0, 0), H_-1),   cx0 = min(max(x0, 0), W_-1);
        int cy1 = min(max(y0+1, 0), H_-1), cx1 = min(max(x0+1, 0), W_-1);
        int se = k*64 + px;
        s_w[se]  = make_float4(w00, w01, w10, w11);
        s_i0[se] = cy0*W_ + cx0;
        s_d[se]  = (cx1 - cx0) | (((cy1 - cy0)*W_) << 16);
    }
    __syncthreads();

    // ---------- Phase 3: main DCN (64px x 64o x 576) ----------
    float4 acc[8];
#pragma unroll
    for (int j = 0; j < 8; j++) acc[j] = make_float4(0.f, 0.f, 0.f, 0.f);

    for (int k = 0; k < K_; k++) {
        // stage A: 64 px x 8 c8 = 512 elems
        for (int e = tid; e < 512; e += 128) {
            int c8 = e & 7, px = e >> 3;
            int se = k*64 + px;
            float4 wv = s_w[se];
            int i0 = s_i0[se];
            int d  = s_d[se];
            int dx  = d & 0xffff;
            int dyw = d >> 16;
            const __half* p00 = xh + (size_t)i0*C_ + c8*8;
            uint4 A  = *(const uint4*)(p00);
            uint4 Bb = *(const uint4*)(p00 + dx*C_);
            uint4 Cc = *(const uint4*)(p00 + dyw*C_);
            uint4 Dd = *(const uint4*)(p00 + (size_t)(dyw+dx)*C_);
            __half2 w00h = __float2half2_rn(wv.x);
            __half2 w01h = __float2half2_rn(wv.y);
            __half2 w10h = __float2half2_rn(wv.z);
            __half2 w11h = __float2half2_rn(wv.w);
            const __half2* Ah = (const __half2*)&A;
            const __half2* Bh = (const __half2*)&Bb;
            const __half2* Ch = (const __half2*)&Cc;
            const __half2* Dh = (const __half2*)&Dd;
            uint4 r;
            __half2* Rh = (__half2*)&r;
#pragma unroll
            for (int q = 0; q < 4; q++) {
                __half2 t = __hmul2(w00h, Ah[q]);
                t = __hfma2(w01h, Bh[q], t);
                t = __hfma2(w10h, Ch[q], t);
                t = __hfma2(w11h, Dh[q], t);
                Rh[q] = t;
            }
            xs4[px*9 + c8] = r;
        }
        {
            const uint4* src = g_wt3h4 + (size_t)k*512;
            for (int e = tid; e < 512; e += 128) bB4[e] = src[e];
        }
        __syncthreads();
#pragma unroll
        for (int ks = 0; ks < 4; ks++) {
            uint32_t a0, a1, a2, a3;
            ldsm4(a0, a1, a2, a3, aBase + ks*32);
#pragma unroll
            for (int j2 = 0; j2 < 4; j2++) {
                uint4 bf = bB4[(ks*4 + j2)*32 + lane];
                mma16(acc[2*j2],     a0, a1, a2, a3, bf.x, bf.y);
                mma16(acc[2*j2 + 1], a0, a1, a2, a3, bf.z, bf.w);
            }
        }
        __syncthreads();
    }

    // ---------- Epilogue: NCHW store + bias ----------
#pragma unroll
    for (int j = 0; j < 8; j++) {
        int o = j*8 + tig*2;
        float b0v = __ldg(bias + o);
        float b1v = __ldg(bias + o + 1);
        size_t base0 = (((size_t)b*O_ + o    )*H_ + h)*W_ + w0px;
        size_t base1 = (((size_t)b*O_ + o + 1)*H_ + h)*W_ + w0px;
        out[base0 + row0]     = acc[j].x + b0v;
        out[base1 + row0]     = acc[j].y + b1v;
        out[base0 + row0 + 8] = acc[j].z + b0v;
        out[base1 + row0 + 8] = acc[j].w + b1v;
    }
}

extern "C" void kernel_launch(void* const* d_in, const int* in_sizes, int n_in,
                              void* d_out, int out_size) {
    const float* x         = (const float*)d_in[0];
    const float* weight    = (const float*)d_in[1];
    const float* bias      = (const float*)d_in[2];
    const float* om_weight = (const float*)d_in[3];
    const float* om_bias   = (const float*)d_in[4];
    float* out = (float*)d_out;

    int B = in_sizes[0] / (C_*H_*W_);
    if (B < 1) B = 1;
    if (B > Bmax) B = Bmax;

    cudaFuncSetAttribute(k_dcn, cudaFuncAttributeMaxDynamicSharedMemorySize, SM_TOT);

    k_prep<<<NT_BLKS + NREP_BLKS, 256>>>(x, weight, om_weight);
    k_dcn<<<dim3(H_*2, B), 128, SM_TOT>>>(bias, om_bias, out);
}

// round 15
// speedup vs baseline: 1.2407x; 1.2407x over previous
#include <cuda_runtime.h>
#include <cuda_fp16.h>
#include <math.h>
#include <stdint.h>

#define Bmax 4
#define C_ 64
#define H_ 128
#define W_ 128
#define O_ 64
#define K_ 9
#define HW_ (H_*W_)

__device__ __forceinline__ uint32_t cvt_h2(float hi, float lo) {
    uint32_t r; asm("cvt.rn.f16x2.f32 %0, %1, %2;" : "=r"(r) : "f"(hi), "f"(lo)); return r;
}
__device__ __forceinline__ void mma16(float4 &d, uint32_t a0, uint32_t a1, uint32_t a2, uint32_t a3,
                                      uint32_t b0, uint32_t b1) {
    asm("mma.sync.aligned.m16n8k16.row.col.f32.f16.f16.f32 "
        "{%0,%1,%2,%3},{%4,%5,%6,%7},{%8,%9},{%0,%1,%2,%3};"
        : "+f"(d.x), "+f"(d.y), "+f"(d.z), "+f"(d.w)
        : "r"(a0), "r"(a1), "r"(a2), "r"(a3), "r"(b0), "r"(b1));
}
__device__ __forceinline__ void ldsm4(uint32_t &a0, uint32_t &a1, uint32_t &a2, uint32_t &a3,
                                      uint32_t addr) {
    asm volatile("ldmatrix.sync.aligned.m8n8.x4.shared.b16 {%0,%1,%2,%3}, [%4];"
                 : "=r"(a0), "=r"(a1), "=r"(a2), "=r"(a3) : "r"(addr));
}

// ---------------- device scratch ----------------
__device__ __align__(16) __half g_xh[Bmax*HW_*C_ + 16384];  // NHWC x (fp16), padded
__device__ uint4 g_wt3h4[K_*4*4*32];          // main: [k][ks(4)][j2(4)][lane]
__device__ uint4 g_w1h4[K_*4*2*32];           // om:   [kk(9)][ks(4)][j2(2)][lane]

// ---------------- merged prep: transpose->fp16 NHWC + repack ----------------
#define NT_BLKS 1024
#define NREP4 (K_*4*4*32 + K_*4*2*32)
#define NREP_BLKS ((NREP4 + 255)/256)

__global__ __launch_bounds__(256)
void k_prep(const float* __restrict__ x, const float* __restrict__ wgt,
            const float* __restrict__ omw) {
    int bid = blockIdx.x;
    if (bid < NT_BLKS) {
        __shared__ float t[2][2][32][33];
        int wb = bid & 3;
        int h0 = ((bid >> 2) & 63) * 2;
        int b  = bid >> 8;
        int w0 = wb * 32;
        int tid = threadIdx.x;
        int r  = tid >> 3;
        int q  = tid & 7;
#pragma unroll
        for (int hh = 0; hh < 2; hh++) {
            float4 v0 = *(const float4*)(x + ((size_t)(b*C_ + r     )*H_ + h0 + hh)*W_ + w0 + q*4);
            float4 v1 = *(const float4*)(x + ((size_t)(b*C_ + 32 + r)*H_ + h0 + hh)*W_ + w0 + q*4);
            t[hh][0][r][q*4] = v0.x; t[hh][0][r][q*4+1] = v0.y; t[hh][0][r][q*4+2] = v0.z; t[hh][0][r][q*4+3] = v0.w;
            t[hh][1][r][q*4] = v1.x; t[hh][1][r][q*4+1] = v1.y; t[hh][1][r][q*4+2] = v1.z; t[hh][1][r][q*4+3] = v1.w;
        }
        __syncthreads();
#pragma unroll
        for (int hh = 0; hh < 2; hh++) {
            float4 o0, o1;
            o0.x = t[hh][0][q*4][r]; o0.y = t[hh][0][q*4+1][r]; o0.z = t[hh][0][q*4+2][r]; o0.w = t[hh][0][q*4+3][r];
            o1.x = t[hh][1][q*4][r]; o1.y = t[hh][1][q*4+1][r]; o1.z = t[hh][1][q*4+2][r]; o1.w = t[hh][1][q*4+3][r];
            __half* dst = g_xh + ((size_t)(b*H_ + h0 + hh)*W_ + w0 + r)*C_;
            *(uint2*)(dst + q*4)      = make_uint2(cvt_h2(o0.y, o0.x), cvt_h2(o0.w, o0.z));
            *(uint2*)(dst + 32 + q*4) = make_uint2(cvt_h2(o1.y, o1.x), cvt_h2(o1.w, o1.z));
        }
    } else {
        int f = (bid - NT_BLKS)*256 + threadIdx.x;
        if (f < K_*4*4*32) {              // main weights: [k][ks][j2(2b)][lane(5b)]
            int lane = f & 31;
            int j2 = (f >> 5) & 3;
            int ks = (f >> 7) & 3;
            int k  = f >> 9;
            int c0 = ks*16 + 2*(lane & 3);
            uint4 r;
            {
                int o = (2*j2)*8 + (lane >> 2);
                const float* wb2 = wgt + (size_t)o*C_*K_;
                r.x = cvt_h2(wb2[(c0+1)*K_ + k], wb2[c0*K_ + k]);
                r.y = cvt_h2(wb2[(c0+9)*K_ + k], wb2[(c0+8)*K_ + k]);
            }
            {
                int o = (2*j2+1)*8 + (lane >> 2);
                const float* wb2 = wgt + (size_t)o*C_*K_;
                r.z = cvt_h2(wb2[(c0+1)*K_ + k], wb2[c0*K_ + k]);
                r.w = cvt_h2(wb2[(c0+9)*K_ + k], wb2[(c0+8)*K_ + k]);
            }
            g_wt3h4[f] = r;
        } else if (f < NREP4) {           // om weights: [kk][ks(2b)][j2(1b)][lane(5b)]
            int f2 = f - K_*4*4*32;
            int lane = f2 & 31;
            int j2 = (f2 >> 5) & 1;
            int ks = (f2 >> 6) & 3;
            int kk = f2 >> 8;
            int c0 = ks*16 + 2*(lane & 3);
            uint4 r = make_uint4(0, 0, 0, 0);
            {
                int oc = (2*j2)*8 + (lane >> 2);
                if (oc < 27) {
                    const float* wb2 = omw + (size_t)oc*C_*K_;
                    r.x = cvt_h2(wb2[(c0+1)*K_ + kk], wb2[c0*K_ + kk]);
                    r.y = cvt_h2(wb2[(c0+9)*K_ + kk], wb2[(c0+8)*K_ + kk]);
                }
            }
            {
                int oc = (2*j2+1)*8 + (lane >> 2);
                if (oc < 27) {
                    const float* wb2 = omw + (size_t)oc*C_*K_;
                    r.z = cvt_h2(wb2[(c0+1)*K_ + kk], wb2[c0*K_ + kk]);
                    r.w = cvt_h2(wb2[(c0+9)*K_ + kk], wb2[(c0+8)*K_ + kk]);
                }
            }
            g_w1h4[f2] = r;
        }
    }
}

// ---------------- fused DCN: one block per (b, h) row, 512 threads ----------------
// warp (m, n): m = w & 7 -> px band 16m ; n = w >> 3 -> o half 32n
// smem byte layout (58.7 KB -> 2 CTAs/SM = 1024 thr/SM = 32 warps/SM)
#define SM_XS  0        // 18720 B : A tile half[130 px][72 c] (pitch 144B); om_s float[128][36] unions
#define SM_B   18720    // 12288 B : B fragments (ph1: 3 kx x 4KB; ph3: 8KB)
#define SM_SW  31008    // 18432 B : float4[9][128] corner weights
#define SM_I0  49440    // 4608  B : int[9][128]
#define SM_DD  54048    // 4608  B : int[9][128]
#define SM_TOT 58656

__global__ __launch_bounds__(512, 2)
void k_dcn(const float* __restrict__ bias, const float* __restrict__ om_bias,
           float* __restrict__ out) {
    extern __shared__ char sm[];
    uint4*    xs4   = (uint4*)(sm + SM_XS);      // row pitch 9 uint4
    float*    om_s  = (float*)(sm + SM_XS);      // stride 36 floats (144B pitch)
    uint4*    bB4   = (uint4*)(sm + SM_B);
    float4*   s_w   = (float4*)(sm + SM_SW);
    int*      s_i0  = (int*)(sm + SM_I0);
    int*      s_d   = (int*)(sm + SM_DD);

    const int tid  = threadIdx.x;
    const int lane = tid & 31;
    const int wid  = tid >> 5;                   // 0..15
    const int m    = wid & 7;                    // px band
    const int n    = wid >> 3;                   // o half
    const int tg   = lane >> 2;
    const int tig  = lane & 3;
    const int h    = blockIdx.x;
    const int b    = blockIdx.y;
    const int row0 = m*16 + tg;
    const __half* xh = g_xh + (size_t)b*HW_*C_;

    const uint32_t smb = (uint32_t)__cvta_generic_to_shared(sm);
    const int laneRow  = ((lane >> 3) & 1)*8 + (lane & 7);
    const int chunkOff = (lane >> 4)*16;
    const uint32_t aBase = smb + SM_XS + (uint32_t)(m*16 + laneRow)*144 + chunkOff;

    // ---------- Phase 1: offset/mask conv (128px x 32oc x 576), 3 row-stagings ----------
    // warp n handles j2g = n -> oc = (2n)*8..(2n+1)*8+7
    float4 acc1[2];
    acc1[0] = make_float4(0.f, 0.f, 0.f, 0.f);
    acc1[1] = make_float4(0.f, 0.f, 0.f, 0.f);

    for (int ky = 0; ky < 3; ky++) {
        int yy = h + ky - 1;
        for (int e = tid; e < 1040; e += 512) {
            int c8 = e & 7, r = e >> 3;
            int xx = r - 1;
            uint4 v = make_uint4(0, 0, 0, 0);
            if (yy >= 0 && yy < H_ && xx >= 0 && xx < W_)
                v = *(const uint4*)(xh + ((size_t)yy*W_ + xx)*C_ + c8*8);
            xs4[r*9 + c8] = v;
        }
        {
            const uint4* src = g_w1h4 + (size_t)ky*3*256;
            for (int e = tid; e < 768; e += 512) bB4[e] = src[e];
        }
        __syncthreads();
#pragma unroll
        for (int ks = 0; ks < 4; ks++) {
#pragma unroll
            for (int kx = 0; kx < 3; kx++) {
                uint32_t a0, a1, a2, a3;
                ldsm4(a0, a1, a2, a3, aBase + kx*144 + ks*32);
                uint4 bf = bB4[kx*256 + (ks*2 + n)*32 + lane];
                mma16(acc1[0], a0, a1, a2, a3, bf.x, bf.y);
                mma16(acc1[1], a0, a1, a2, a3, bf.z, bf.w);
            }
        }
        __syncthreads();
    }

    // ---------- Phase 2a: write om fragments (stride 36 floats); warp n -> j = 2n+jl ----------
#pragma unroll
    for (int jl = 0; jl < 2; jl++) {
        int col = (2*n + jl)*8 + tig*2;
        *(float2*)(om_s + row0*36 + col)     = make_float2(acc1[jl].x, acc1[jl].y);
        *(float2*)(om_s + (row0+8)*36 + col) = make_float2(acc1[jl].z, acc1[jl].w);
    }
    __syncthreads();

    // ---------- Phase 2b: bilinear sampling prep per (px, k) ----------
    for (int e = tid; e < 1152; e += 512) {
        int px = e & 127, k = e >> 7;
        int ky = k / 3, kx = k - 3*ky;
        float oy = om_s[px*36 + k]      + __ldg(om_bias + k);
        float ox = om_s[px*36 + 9 + k]  + __ldg(om_bias + 9 + k);
        float mz = om_s[px*36 + 18 + k] + __ldg(om_bias + 18 + k);
        float mk = 1.f / (1.f + expf(-mz));
        float pyf = oy + (float)(h - 1 + ky);
        float pxf = ox + (float)(px - 1 + kx);
        float y0f = floorf(pyf), x0f = floorf(pxf);
        float ly = pyf - y0f, lx = pxf - x0f;
        int y0 = (int)y0f, x0 = (int)x0f;
        bool vy0 = (y0 >= 0)   & (y0 < H_);
        bool vy1 = (y0 >= -1)  & (y0 < H_-1);
        bool vx0 = (x0 >= 0)   & (x0 < W_);
        bool vx1 = (x0 >= -1)  & (x0 < W_-1);
        float w00 = (1.f-ly)*(1.f-lx)*mk * (float)(vy0 & vx0);
        float w01 = (1.f-ly)*lx*mk       * (float)(vy0 & vx1);
        float w10 = ly*(1.f-lx)*mk       * (float)(vy1 & vx0);
        float w11 = ly*lx*mk             * (float)(vy1 & vx1);
        int cy0 = min(max(y0, 0), H_-1),   cx0 = min(max(x0, 0), W_-1);
        int cy1 = min(max(y0+1, 0), H_-1), cx1 = min(max(x0+1, 0), W_-1);
        s_w[e]  = make_float4(w00, w01, w10, w11);
        s_i0[e] = cy0*W_ + cx0;
        s_d[e]  = (cx1 - cx0) | (((cy1 - cy0)*W_) << 16);
    }
    __syncthreads();

    // ---------- Phase 3: main DCN (128px x 64o x 576); warp n -> j2g = 2n+j2l ----------
    float4 acc[4];
#pragma unroll
    for (int j = 0; j < 4; j++) acc[j] = make_float4(0.f, 0.f, 0.f, 0.f);

    for (int k = 0; k < K_; k++) {
        // stage A: 128 px x 8 c8 = 1024 elems / 512 threads = 2 each
        for (int e = tid; e < 1024; e += 512) {
            int c8 = e & 7, px = e >> 3;
            int se = k*128 + px;
            float4 wv = s_w[se];
            int i0 = s_i0[se];
            int d  = s_d[se];
            int dx  = d & 0xffff;
            int dyw = d >> 16;
            const __half* p00 = xh + (size_t)i0*C_ + c8*8;
            uint4 A  = *(const uint4*)(p00);
            uint4 Bb = *(const uint4*)(p00 + dx*C_);
            uint4 Cc = *(const uint4*)(p00 + dyw*C_);
            uint4 Dd = *(const uint4*)(p00 + (size_t)(dyw+dx)*C_);
            __half2 w00h = __float2half2_rn(wv.x);
            __half2 w01h = __float2half2_rn(wv.y);
            __half2 w10h = __float2half2_rn(wv.z);
            __half2 w11h = __float2half2_rn(wv.w);
            const __half2* Ah = (const __half2*)&A;
            const __half2* Bh = (const __half2*)&Bb;
            const __half2* Ch = (const __half2*)&Cc;
            const __half2* Dh = (const __half2*)&Dd;
            uint4 r;
            __half2* Rh = (__half2*)&r;
#pragma unroll
            for (int q = 0; q < 4; q++) {
                __half2 t = __hmul2(w00h, Ah[q]);
                t = __hfma2(w01h, Bh[q], t);
                t = __hfma2(w10h, Ch[q], t);
                t = __hfma2(w11h, Dh[q], t);
                Rh[q] = t;
            }
            xs4[px*9 + c8] = r;
        }
        {
            const uint4* src = g_wt3h4 + (size_t)k*512;
            for (int e = tid; e < 512; e += 512) bB4[e] = src[e];
        }
        __syncthreads();
#pragma unroll
        for (int ks = 0; ks < 4; ks++) {
            uint32_t a0, a1, a2, a3;
            ldsm4(a0, a1, a2, a3, aBase + ks*32);
#pragma unroll
            for (int j2l = 0; j2l < 2; j2l++) {
                uint4 bf = bB4[(ks*4 + 2*n + j2l)*32 + lane];
                mma16(acc[2*j2l],     a0, a1, a2, a3, bf.x, bf.y);
                mma16(acc[2*j2l + 1], a0, a1, a2, a3, bf.z, bf.w);
            }
        }
        __syncthreads();
    }

    // ---------- Epilogue: NCHW store + bias; warp n -> o = (4n+jl)*8 + tig*2 ----------
#pragma unroll
    for (int jl = 0; jl < 4; jl++) {
        int o = (4*n + jl)*8 + tig*2;
        float b0v = __ldg(bias + o);
        float b1v = __ldg(bias + o + 1);
        size_t base0 = (((size_t)b*O_ + o    )*H_ + h)*W_;
        size_t base1 = (((size_t)b*O_ + o + 1)*H_ + h)*W_;
        out[base0 + row0]     = acc[jl].x + b0v;
        out[base1 + row0]     = acc[jl].y + b1v;
        out[base0 + row0 + 8] = acc[jl].z + b0v;
        out[base1 + row0 + 8] = acc[jl].w + b1v;
    }
}

extern "C" void kernel_launch(void* const* d_in, const int* in_sizes, int n_in,
                              void* d_out, int out_size) {
    const float* x         = (const float*)d_in[0];
    const float* weight    = (const float*)d_in[1];
    const float* bias      = (const float*)d_in[2];
    const float* om_weight = (const float*)d_in[3];
    const float* om_bias   = (const float*)d_in[4];
    float* out = (float*)d_out;

    int B = in_sizes[0] / (C_*H_*W_);
    if (B < 1) B = 1;
    if (B > Bmax) B = Bmax;

    cudaFuncSetAttribute(k_dcn, cudaFuncAttributeMaxDynamicSharedMemorySize, SM_TOT);

    k_prep<<<NT_BLKS + NREP_BLKS, 256>>>(x, weight, om_weight);
    k_dcn<<<dim3(H_, B), 512, SM_TOT>>>(bias, om_bias, out);
}

// round 16
// speedup vs baseline: 1.2798x; 1.0315x over previous
#include <cuda_runtime.h>
#include <cuda_fp16.h>
#include <math.h>
#include <stdint.h>

#define Bmax 4
#define C_ 64
#define H_ 128
#define W_ 128
#define O_ 64
#define K_ 9
#define HW_ (H_*W_)

__device__ __forceinline__ uint32_t cvt_h2(float hi, float lo) {
    uint32_t r; asm("cvt.rn.f16x2.f32 %0, %1, %2;" : "=r"(r) : "f"(hi), "f"(lo)); return r;
}
__device__ __forceinline__ void mma16(float4 &d, uint32_t a0, uint32_t a1, uint32_t a2, uint32_t a3,
                                      uint32_t b0, uint32_t b1) {
    asm("mma.sync.aligned.m16n8k16.row.col.f32.f16.f16.f32 "
        "{%0,%1,%2,%3},{%4,%5,%6,%7},{%8,%9},{%0,%1,%2,%3};"
        : "+f"(d.x), "+f"(d.y), "+f"(d.z), "+f"(d.w)
        : "r"(a0), "r"(a1), "r"(a2), "r"(a3), "r"(b0), "r"(b1));
}
__device__ __forceinline__ void ldsm4(uint32_t &a0, uint32_t &a1, uint32_t &a2, uint32_t &a3,
                                      uint32_t addr) {
    asm volatile("ldmatrix.sync.aligned.m8n8.x4.shared.b16 {%0,%1,%2,%3}, [%4];"
                 : "=r"(a0), "=r"(a1), "=r"(a2), "=r"(a3) : "r"(addr));
}

// ---------------- device scratch ----------------
__device__ __align__(16) __half g_xh[Bmax*HW_*C_ + 16384];  // NHWC x (fp16), padded
__device__ uint4 g_wt3h4[K_*4*4*32];          // main: [k][ks(4)][j2(4)][lane]
__device__ uint4 g_w1h4[K_*4*2*32];           // om:   [kk(9)][ks(4)][j2(2)][lane]

// ---------------- merged prep: transpose->fp16 NHWC + repack ----------------
#define NT_BLKS 1024
#define NREP4 (K_*4*4*32 + K_*4*2*32)
#define NREP_BLKS ((NREP4 + 255)/256)

__global__ __launch_bounds__(256)
void k_prep(const float* __restrict__ x, const float* __restrict__ wgt,
            const float* __restrict__ omw) {
    int bid = blockIdx.x;
    if (bid < NT_BLKS) {
        __shared__ float t[2][2][32][33];
        int wb = bid & 3;
        int h0 = ((bid >> 2) & 63) * 2;
        int b  = bid >> 8;
        int w0 = wb * 32;
        int tid = threadIdx.x;
        int r  = tid >> 3;
        int q  = tid & 7;
#pragma unroll
        for (int hh = 0; hh < 2; hh++) {
            float4 v0 = *(const float4*)(x + ((size_t)(b*C_ + r     )*H_ + h0 + hh)*W_ + w0 + q*4);
            float4 v1 = *(const float4*)(x + ((size_t)(b*C_ + 32 + r)*H_ + h0 + hh)*W_ + w0 + q*4);
            t[hh][0][r][q*4] = v0.x; t[hh][0][r][q*4+1] = v0.y; t[hh][0][r][q*4+2] = v0.z; t[hh][0][r][q*4+3] = v0.w;
            t[hh][1][r][q*4] = v1.x; t[hh][1][r][q*4+1] = v1.y; t[hh][1][r][q*4+2] = v1.z; t[hh][1][r][q*4+3] = v1.w;
        }
        __syncthreads();
#pragma unroll
        for (int hh = 0; hh < 2; hh++) {
            float4 o0, o1;
            o0.x = t[hh][0][q*4][r]; o0.y = t[hh][0][q*4+1][r]; o0.z = t[hh][0][q*4+2][r]; o0.w = t[hh][0][q*4+3][r];
            o1.x = t[hh][1][q*4][r]; o1.y = t[hh][1][q*4+1][r]; o1.z = t[hh][1][q*4+2][r]; o1.w = t[hh][1][q*4+3][r];
            __half* dst = g_xh + ((size_t)(b*H_ + h0 + hh)*W_ + w0 + r)*C_;
            *(uint2*)(dst + q*4)      = make_uint2(cvt_h2(o0.y, o0.x), cvt_h2(o0.w, o0.z));
            *(uint2*)(dst + 32 + q*4) = make_uint2(cvt_h2(o1.y, o1.x), cvt_h2(o1.w, o1.z));
        }
    } else {
        int f = (bid - NT_BLKS)*256 + threadIdx.x;
        if (f < K_*4*4*32) {              // main weights: [k][ks][j2(2b)][lane(5b)]
            int lane = f & 31;
            int j2 = (f >> 5) & 3;
            int ks = (f >> 7) & 3;
            int k  = f >> 9;
            int c0 = ks*16 + 2*(lane & 3);
            uint4 r;
            {
                int o = (2*j2)*8 + (lane >> 2);
                const float* wb2 = wgt + (size_t)o*C_*K_;
                r.x = cvt_h2(wb2[(c0+1)*K_ + k], wb2[c0*K_ + k]);
                r.y = cvt_h2(wb2[(c0+9)*K_ + k], wb2[(c0+8)*K_ + k]);
            }
            {
                int o = (2*j2+1)*8 + (lane >> 2);
                const float* wb2 = wgt + (size_t)o*C_*K_;
                r.z = cvt_h2(wb2[(c0+1)*K_ + k], wb2[c0*K_ + k]);
                r.w = cvt_h2(wb2[(c0+9)*K_ + k], wb2[(c0+8)*K_ + k]);
            }
            g_wt3h4[f] = r;
        } else if (f < NREP4) {           // om weights: [kk][ks(2b)][j2(1b)][lane(5b)]
            int f2 = f - K_*4*4*32;
            int lane = f2 & 31;
            int j2 = (f2 >> 5) & 1;
            int ks = (f2 >> 6) & 3;
            int kk = f2 >> 8;
            int c0 = ks*16 + 2*(lane & 3);
            uint4 r = make_uint4(0, 0, 0, 0);
            {
                int oc = (2*j2)*8 + (lane >> 2);
                if (oc < 27) {
                    const float* wb2 = omw + (size_t)oc*C_*K_;
                    r.x = cvt_h2(wb2[(c0+1)*K_ + kk], wb2[c0*K_ + kk]);
                    r.y = cvt_h2(wb2[(c0+9)*K_ + kk], wb2[(c0+8)*K_ + kk]);
                }
            }
            {
                int oc = (2*j2+1)*8 + (lane >> 2);
                if (oc < 27) {
                    const float* wb2 = omw + (size_t)oc*C_*K_;
                    r.z = cvt_h2(wb2[(c0+1)*K_ + kk], wb2[c0*K_ + kk]);
                    r.w = cvt_h2(wb2[(c0+9)*K_ + kk], wb2[(c0+8)*K_ + kk]);
                }
            }
            g_w1h4[f2] = r;
        }
    }
}

// ---------------- fused DCN: one block per (b, h) row, 512 threads, double-buffered ----------------
// warp (m, n): m = w & 7 -> px band 16m ; n = w >> 3 -> o half 32n
// smem (89.7 KB -> 2 CTAs/SM = 32 warps/SM)
#define SM_A0  0        // 18720 B : A tile buf0, half[130 px][72 c] (pitch 144B); om_s unions here
#define SM_A1  18720    // 18720 B : A tile buf1
#define SM_B0  37440    // 12288 B : B frag buf0 (ph1: 3 kx x 4KB; ph3: 8KB)
#define SM_B1  49728    // 12288 B : B frag buf1
#define SM_SW  62016    // 18432 B : float4[9][128] corner weights
#define SM_I0  80448    // 4608  B : int[9][128]
#define SM_DD  85056    // 4608  B : int[9][128]
#define SM_TOT 89664

__global__ __launch_bounds__(512, 2)
void k_dcn(const float* __restrict__ bias, const float* __restrict__ om_bias,
           float* __restrict__ out) {
    extern __shared__ char sm[];
    float*    om_s  = (float*)(sm + SM_A0);      // stride-36 floats; A0 dead when used
    float4*   s_w   = (float4*)(sm + SM_SW);
    int*      s_i0  = (int*)(sm + SM_I0);
    int*      s_d   = (int*)(sm + SM_DD);

    const int tid  = threadIdx.x;
    const int lane = tid & 31;
    const int wid  = tid >> 5;
    const int m    = wid & 7;
    const int n    = wid >> 3;
    const int tg   = lane >> 2;
    const int tig  = lane & 3;
    const int h    = blockIdx.x;
    const int b    = blockIdx.y;
    const int row0 = m*16 + tg;
    const __half* xh = g_xh + (size_t)b*HW_*C_;

    const uint32_t smb = (uint32_t)__cvta_generic_to_shared(sm);
    const int laneRow  = ((lane >> 3) & 1)*8 + (lane & 7);
    const int chunkOff = (lane >> 4)*16;
    const uint32_t aFragOff = (uint32_t)(m*16 + laneRow)*144 + chunkOff;

    auto bufA4 = [&](int i) { return (uint4*)(sm + (i ? SM_A1 : SM_A0)); };
    auto bufB4 = [&](int i) { return (uint4*)(sm + (i ? SM_B1 : SM_B0)); };
    auto aBase = [&](int i) { return smb + (i ? SM_A1 : SM_A0) + aFragOff; };

    // ---------- Phase 1: offset/mask conv (128px x 32oc x 576), pipelined over ky ----------
    float4 acc1[2];
    acc1[0] = make_float4(0.f, 0.f, 0.f, 0.f);
    acc1[1] = make_float4(0.f, 0.f, 0.f, 0.f);

    auto stageA1 = [&](int ky, int buf) {
        int yy = h + ky - 1;
        uint4* xs4 = bufA4(buf);
        for (int e = tid; e < 1040; e += 512) {
            int c8 = e & 7, r = e >> 3;
            int xx = r - 1;
            uint4 v = make_uint4(0, 0, 0, 0);
            if (yy >= 0 && yy < H_ && xx >= 0 && xx < W_)
                v = *(const uint4*)(xh + ((size_t)yy*W_ + xx)*C_ + c8*8);
            xs4[r*9 + c8] = v;
        }
    };
    auto stageB1 = [&](int ky, int buf) {
        const uint4* src = g_w1h4 + (size_t)ky*3*256;
        uint4* dst = bufB4(buf);
        for (int e = tid; e < 768; e += 512) dst[e] = src[e];
    };

    stageA1(0, 0); stageB1(0, 0);
    __syncthreads();
    for (int ky = 0; ky < 3; ky++) {
        int cur = ky & 1;
        if (ky < 2) { stageA1(ky + 1, cur ^ 1); stageB1(ky + 1, cur ^ 1); }
        const uint4* bB = bufB4(cur);
        uint32_t ab = aBase(cur);
#pragma unroll
        for (int ks = 0; ks < 4; ks++) {
#pragma unroll
            for (int kx = 0; kx < 3; kx++) {
                uint32_t a0, a1, a2, a3;
                ldsm4(a0, a1, a2, a3, ab + kx*144 + ks*32);
                uint4 bf = bB[kx*256 + (ks*2 + n)*32 + lane];
                mma16(acc1[0], a0, a1, a2, a3, bf.x, bf.y);
                mma16(acc1[1], a0, a1, a2, a3, bf.z, bf.w);
            }
        }
        __syncthreads();
    }

    // ---------- Phase 2a: write om fragments (stride 36 floats) into A0 (dead) ----------
#pragma unroll
    for (int jl = 0; jl < 2; jl++) {
        int col = (2*n + jl)*8 + tig*2;
        *(float2*)(om_s + row0*36 + col)     = make_float2(acc1[jl].x, acc1[jl].y);
        *(float2*)(om_s + (row0+8)*36 + col) = make_float2(acc1[jl].z, acc1[jl].w);
    }
    __syncthreads();

    // ---------- Phase 2b: bilinear sampling prep per (px, k) ----------
    for (int e = tid; e < 1152; e += 512) {
        int px = e & 127, k = e >> 7;
        int ky = k / 3, kx = k - 3*ky;
        float oy = om_s[px*36 + k]      + __ldg(om_bias + k);
        float ox = om_s[px*36 + 9 + k]  + __ldg(om_bias + 9 + k);
        float mz = om_s[px*36 + 18 + k] + __ldg(om_bias + 18 + k);
        float mk = 1.f / (1.f + expf(-mz));
        float pyf = oy + (float)(h - 1 + ky);
        float pxf = ox + (float)(px - 1 + kx);
        float y0f = floorf(pyf), x0f = floorf(pxf);
        float ly = pyf - y0f, lx = pxf - x0f;
        int y0 = (int)y0f, x0 = (int)x0f;
        bool vy0 = (y0 >= 0)   & (y0 < H_);
        bool vy1 = (y0 >= -1)  & (y0 < H_-1);
        bool vx0 = (x0 >= 0)   & (x0 < W_);
        bool vx1 = (x0 >= -1)  & (x0 < W_-1);
        float w00 = (1.f-ly)*(1.f-lx)*mk * (float)(vy0 & vx0);
        float w01 = (1.f-ly)*lx*mk       * (float)(vy0 & vx1);
        float w10 = ly*(1.f-lx)*mk       * (float)(vy1 & vx0);
        float w11 = ly*lx*mk             * (float)(vy1 & vx1);
        int cy0 = min(max(y0, 0), H_-1),   cx0 = min(max(x0, 0), W_-1);
        int cy1 = min(max(y0+1, 0), H_-1), cx1 = min(max(x0+1, 0), W_-1);
        s_w[e]  = make_float4(w00, w01, w10, w11);
        s_i0[e] = cy0*W_ + cx0;
        s_d[e]  = (cx1 - cx0) | (((cy1 - cy0)*W_) << 16);
    }
    __syncthreads();

    // ---------- Phase 3: main DCN (128px x 64o x 576), pipelined over taps ----------
    float4 acc[4];
#pragma unroll
    for (int j = 0; j < 4; j++) acc[j] = make_float4(0.f, 0.f, 0.f, 0.f);

    auto stageA3 = [&](int k, int buf) {
        uint4* xs4 = bufA4(buf);
        for (int e = tid; e < 1024; e += 512) {
            int c8 = e & 7, px = e >> 3;
            int se = k*128 + px;
            float4 wv = s_w[se];
            int i0 = s_i0[se];
            int d  = s_d[se];
            int dx  = d & 0xffff;
            int dyw = d >> 16;
            const __half* p00 = xh + (size_t)i0*C_ + c8*8;
            uint4 A  = *(const uint4*)(p00);
            uint4 Bb = *(const uint4*)(p00 + dx*C_);
            uint4 Cc = *(const uint4*)(p00 + dyw*C_);
            uint4 Dd = *(const uint4*)(p00 + (size_t)(dyw+dx)*C_);
            __half2 w00h = __float2half2_rn(wv.x);
            __half2 w01h = __float2half2_rn(wv.y);
            __half2 w10h = __float2half2_rn(wv.z);
            __half2 w11h = __float2half2_rn(wv.w);
            const __half2* Ah = (const __half2*)&A;
            const __half2* Bh = (const __half2*)&Bb;
            const __half2* Ch = (const __half2*)&Cc;
            const __half2* Dh = (const __half2*)&Dd;
            uint4 r;
            __half2* Rh = (__half2*)&r;
#pragma unroll
            for (int q = 0; q < 4; q++) {
                __half2 t = __hmul2(w00h, Ah[q]);
                t = __hfma2(w01h, Bh[q], t);
                t = __hfma2(w10h, Ch[q], t);
                t = __hfma2(w11h, Dh[q], t);
                Rh[q] = t;
            }
            xs4[px*9 + c8] = r;
        }
    };
    auto stageB3 = [&](int k, int buf) {
        const uint4* src = g_wt3h4 + (size_t)k*512;
        uint4* dst = bufB4(buf);
        for (int e = tid; e < 512; e += 512) dst[e] = src[e];
    };

    stageA3(0, 1); stageB3(0, 1);     // start in buf1 (A0 held om_s; now dead, but buf1 is free anyway)
    __syncthreads();
    for (int k = 0; k < K_; k++) {
        int cur = (k & 1) ^ 1;        // k=0 -> buf1, k=1 -> buf0, ...
        if (k < K_ - 1) { stageA3(k + 1, cur ^ 1); stageB3(k + 1, cur ^ 1); }
        const uint4* bB = bufB4(cur);
        uint32_t ab = aBase(cur);
#pragma unroll
        for (int ks = 0; ks < 4; ks++) {
            uint32_t a0, a1, a2, a3;
            ldsm4(a0, a1, a2, a3, ab + ks*32);
#pragma unroll
            for (int j2l = 0; j2l < 2; j2l++) {
                uint4 bf = bB[(ks*4 + 2*n + j2l)*32 + lane];
                mma16(acc[2*j2l],     a0, a1, a2, a3, bf.x, bf.y);
                mma16(acc[2*j2l + 1], a0, a1, a2, a3, bf.z, bf.w);
            }
        }
        __syncthreads();
    }

    // ---------- Epilogue: NCHW store + bias ----------
#pragma unroll
    for (int jl = 0; jl < 4; jl++) {
        int o = (4*n + jl)*8 + tig*2;
        float b0v = __ldg(bias + o);
        float b1v = __ldg(bias + o + 1);
        size_t base0 = (((size_t)b*O_ + o    )*H_ + h)*W_;
        size_t base1 = (((size_t)b*O_ + o + 1)*H_ + h)*W_;
        out[base0 + row0]     = acc[jl].x + b0v;
        out[base1 + row0]     = acc[jl].y + b1v;
        out[base0 + row0 + 8] = acc[jl].z + b0v;
        out[base1 + row0 + 8] = acc[jl].w + b1v;
    }
}

extern "C" void kernel_launch(void* const* d_in, const int* in_sizes, int n_in,
                              void* d_out, int out_size) {
    const float* x         = (const float*)d_in[0];
    const float* weight    = (const float*)d_in[1];
    const float* bias      = (const float*)d_in[2];
    const float* om_weight = (const float*)d_in[3];
    const float* om_bias   = (const float*)d_in[4];
    float* out = (float*)d_out;

    int B = in_sizes[0] / (C_*H_*W_);
    if (B < 1) B = 1;
    if (B > Bmax) B = Bmax;

    cudaFuncSetAttribute(k_dcn, cudaFuncAttributeMaxDynamicSharedMemorySize, SM_TOT);

    k_prep<<<NT_BLKS + NREP_BLKS, 256>>>(x, weight, om_weight);
    k_dcn<<<dim3(H_, B), 512, SM_TOT>>>(bias, om_bias, out);
}